// round 11
// baseline (speedup 1.0000x reference)
#include <cuda_runtime.h>
#include <cuda_fp16.h>

// Problem constants
#define N_  100000
#define E_  1600000
#define DIN 128
#define HH  4
#define DD  32
#define HD  128        // HH*DD
#define NEG 0.2f
#define CAP 96         // per-node bucket capacity (Poisson(16) tail @96 ~ 1e-50)
#define TK  16         // GEMM K-tile

// ---------------- device scratch (no allocations allowed) ----------------
__device__ __half g_fth[(size_t)N_ * HD];   // projected features fp16 (agg gather table)
__device__ float  g_el[N_ * HH];
__device__ float  g_er[N_ * HH];
__device__ int    g_cnt[N_];
__device__ int    g_srcs[(size_t)N_ * CAP]; // src ids bucketed by dst
__device__ int    g_is64;

// ---------------- dtype detect (int32 vs int64) + zero counters ----------
__global__ void k_init(const void* dst) {
    int i = blockIdx.x * blockDim.x + threadIdx.x;
    if (i < N_) g_cnt[i] = 0;
    if (i == 0) {
        const int* p = (const int*)dst;
        int odd_or = 0;
        // If data is int64 (values < 2^31), every odd 32-bit word is 0.
        #pragma unroll 1
        for (int j = 1; j < 64; j += 2) odd_or |= p[j];
        g_is64 = (odd_or == 0) ? 1 : 0;
    }
}

__device__ __forceinline__ int ld_idx(const void* p, int i, int is64) {
    return is64 ? (int)((const long long*)p)[i] : ((const int*)p)[i];
}

// ---------------- bucket scatter (no histogram/scan needed) ----------------
__global__ void k_scatter(const void* __restrict__ src, const void* __restrict__ dst) {
    int base = (blockIdx.x * blockDim.x + threadIdx.x) * 2;
    int is64 = g_is64;
    #pragma unroll
    for (int q = 0; q < 2; q++) {
        int i = base + q;
        if (i >= E_) return;
        int s = ld_idx(src, i, is64);
        int d = ld_idx(dst, i, is64);
        int p = atomicAdd(&g_cnt[d], 1);
        if (p < CAP) g_srcs[(size_t)d * CAP + p] = s;
    }
}

// ---------------- Tensor-core GEMM + fused attn epilogue ----------
// ft[m][n] = sum_k feat[m][k] * W[n][k]; emits fp16 table + el/er directly.
// 3xTF32 split hoisted to smem-store time: smem holds float2(hi, lo); the
// mainloop is pure LDS + MMA (no cvt/sub on the critical path).

__device__ __forceinline__ float tf32r(float x) {
    unsigned r;
    asm("cvt.rna.tf32.f32 %0, %1;" : "=r"(r) : "f"(x));
    return __uint_as_float(r);
}

__device__ __forceinline__ void mma_tf32(float* c,
                                         unsigned a0, unsigned a1, unsigned a2, unsigned a3,
                                         unsigned b0, unsigned b1) {
    asm volatile("mma.sync.aligned.m16n8k8.row.col.f32.tf32.tf32.f32 "
        "{%0,%1,%2,%3}, {%4,%5,%6,%7}, {%8,%9}, {%0,%1,%2,%3};"
        : "+f"(c[0]), "+f"(c[1]), "+f"(c[2]), "+f"(c[3])
        : "r"(a0), "r"(a1), "r"(a2), "r"(a3), "r"(b0), "r"(b1));
}

__global__ void __launch_bounds__(256) k_gemm_tc(const float* __restrict__ A,
                                                 const float* __restrict__ B,
                                                 const float* __restrict__ atl,
                                                 const float* __restrict__ atr) {
    __shared__ float2 Ahl[TK][132];   // (hi, lo) per element, [k][m]
    __shared__ float2 Bhl[TK][132];   // (hi, lo) per element, [k][n]
    __shared__ float sel[128][4];
    __shared__ float ser[128][4];
    int tid = threadIdx.x;
    int lane = tid & 31;
    int warp = tid >> 5;
    int m0b = blockIdx.x * 128;
    int wm = (warp >> 1) * 32;      // warp M offset in block
    int wn = (warp & 1) * 64;       // warp N offset in block

    #pragma unroll
    for (int idx = tid; idx < 512; idx += 256) {
        sel[idx >> 2][idx & 3] = 0.f;
        ser[idx >> 2][idx & 3] = 0.f;
    }

    float c_[2][8][4];
    #pragma unroll
    for (int i = 0; i < 2; i++)
        #pragma unroll
        for (int j = 0; j < 8; j++)
            #pragma unroll
            for (int q = 0; q < 4; q++) c_[i][j][q] = 0.f;

    for (int kt = 0; kt < DIN; kt += TK) {
        #pragma unroll
        for (int l = 0; l < 2; l++) {
            int idx = tid + l * 256;       // 0..511
            int r = idx >> 2, c4 = idx & 3;
            int gm = m0b + r;
            float4 va = make_float4(0.f, 0.f, 0.f, 0.f);
            if (gm < N_) va = *(const float4*)(A + (size_t)gm * DIN + kt + c4 * 4);
            float h0 = tf32r(va.x), h1 = tf32r(va.y), h2 = tf32r(va.z), h3 = tf32r(va.w);
            Ahl[c4 * 4 + 0][r] = make_float2(h0, va.x - h0);
            Ahl[c4 * 4 + 1][r] = make_float2(h1, va.y - h1);
            Ahl[c4 * 4 + 2][r] = make_float2(h2, va.z - h2);
            Ahl[c4 * 4 + 3][r] = make_float2(h3, va.w - h3);
            float4 vb = *(const float4*)(B + (size_t)r * DIN + kt + c4 * 4);
            float g0 = tf32r(vb.x), g1 = tf32r(vb.y), g2 = tf32r(vb.z), g3 = tf32r(vb.w);
            Bhl[c4 * 4 + 0][r] = make_float2(g0, vb.x - g0);
            Bhl[c4 * 4 + 1][r] = make_float2(g1, vb.y - g1);
            Bhl[c4 * 4 + 2][r] = make_float2(g2, vb.z - g2);
            Bhl[c4 * 4 + 3][r] = make_float2(g3, vb.w - g3);
        }
        __syncthreads();
        #pragma unroll
        for (int ks = 0; ks < TK; ks += 8) {
            unsigned ah[2][4], al_[2][4];
            #pragma unroll
            for (int i = 0; i < 2; i++) {
                int r = wm + i * 16 + (lane >> 2);
                int kk = ks + (lane & 3);
                float2 x0 = Ahl[kk][r];
                float2 x1 = Ahl[kk][r + 8];
                float2 x2 = Ahl[kk + 4][r];
                float2 x3 = Ahl[kk + 4][r + 8];
                ah[i][0] = __float_as_uint(x0.x); al_[i][0] = __float_as_uint(x0.y);
                ah[i][1] = __float_as_uint(x1.x); al_[i][1] = __float_as_uint(x1.y);
                ah[i][2] = __float_as_uint(x2.x); al_[i][2] = __float_as_uint(x2.y);
                ah[i][3] = __float_as_uint(x3.x); al_[i][3] = __float_as_uint(x3.y);
            }
            #pragma unroll
            for (int j = 0; j < 8; j++) {
                int cn = wn + j * 8 + (lane >> 2);
                int kk = ks + (lane & 3);
                float2 y0 = Bhl[kk][cn];
                float2 y1 = Bhl[kk + 4][cn];
                unsigned bh0 = __float_as_uint(y0.x), bl0 = __float_as_uint(y0.y);
                unsigned bh1 = __float_as_uint(y1.x), bl1 = __float_as_uint(y1.y);
                #pragma unroll
                for (int i = 0; i < 2; i++) {
                    mma_tf32(c_[i][j], ah[i][0], ah[i][1], ah[i][2], ah[i][3], bh0, bh1);
                    mma_tf32(c_[i][j], al_[i][0], al_[i][1], al_[i][2], al_[i][3], bh0, bh1);
                    mma_tf32(c_[i][j], ah[i][0], ah[i][1], ah[i][2], ah[i][3], bl0, bl1);
                }
            }
        }
        __syncthreads();
    }

    // ---- epilogue: store fp16 ft, accumulate el/er into smem ----
    int h0w = wn >> 5;                // first head covered by this warp (j=0..3)
    #pragma unroll
    for (int i = 0; i < 2; i++) {
        int rloc0 = wm + i * 16 + (lane >> 2);  // local row (0..127)
        int r0 = m0b + rloc0;
        float el_a = 0.f, er_a = 0.f, el_b = 0.f, er_b = 0.f;   // row r0: head h0w, h0w+1
        float el_c = 0.f, er_c = 0.f, el_d = 0.f, er_d = 0.f;   // row r0+8
        #pragma unroll
        for (int j = 0; j < 8; j++) {
            int cn = wn + j * 8 + 2 * (lane & 3);
            float a0 = __ldg(&atl[cn]),     a1 = __ldg(&atl[cn + 1]);
            float b0 = __ldg(&atr[cn]),     b1 = __ldg(&atr[cn + 1]);
            float c0 = c_[i][j][0], c1 = c_[i][j][1];
            float c2 = c_[i][j][2], c3 = c_[i][j][3];
            if (j < 4) {
                el_a += c0 * a0 + c1 * a1;  er_a += c0 * b0 + c1 * b1;
                el_c += c2 * a0 + c3 * a1;  er_c += c2 * b0 + c3 * b1;
            } else {
                el_b += c0 * a0 + c1 * a1;  er_b += c0 * b0 + c1 * b1;
                el_d += c2 * a0 + c3 * a1;  er_d += c2 * b0 + c3 * b1;
            }
            if (r0 < N_)
                *(__half2*)&g_fth[(size_t)r0 * HD + cn] = __floats2half2_rn(c0, c1);
            if (r0 + 8 < N_)
                *(__half2*)&g_fth[(size_t)(r0 + 8) * HD + cn] = __floats2half2_rn(c2, c3);
        }
        atomicAdd(&sel[rloc0][h0w], el_a);     atomicAdd(&ser[rloc0][h0w], er_a);
        atomicAdd(&sel[rloc0][h0w + 1], el_b); atomicAdd(&ser[rloc0][h0w + 1], er_b);
        atomicAdd(&sel[rloc0 + 8][h0w], el_c);     atomicAdd(&ser[rloc0 + 8][h0w], er_c);
        atomicAdd(&sel[rloc0 + 8][h0w + 1], el_d); atomicAdd(&ser[rloc0 + 8][h0w + 1], er_d);
    }
    __syncthreads();
    #pragma unroll
    for (int idx = tid; idx < 512; idx += 256) {
        int r = idx >> 2, h = idx & 3;
        int gm = m0b + r;
        if (gm < N_) {
            g_el[gm * HH + h] = sel[r][h];
            g_er[gm * HH + h] = ser[r][h];
        }
    }
}

// ---------------- fused softmax + aggregation (fp16 gather) ----------------
// 16 lanes per dst node (2 nodes per warp), 8 channels per lane (uint4 = 16B
// gather). MLP=2 edges in flight: same in-flight bytes as the old 32-lane
// MLP=4 scheme but ~35% fewer warp instructions (kernel is issue-bound).
// rst = (sum_i ex_i * ft16[src_i]) / sum_i ex_i + bias  (max-free softmax)
__global__ void k_agg(const float* __restrict__ bias, float* __restrict__ out) {
    int node = (blockIdx.x * blockDim.x + threadIdx.x) >> 4;
    if (node >= N_) return;
    int sub = threadIdx.x & 15;      // lane within node group
    int h = sub >> 2;                // head (4 lanes per head, 8 ch each)
    // loop-independent loads issued up front
    float erh = __ldg(&g_er[node * HH + h]);
    float4 b0v = __ldg(&((const float4*)bias)[sub * 2]);
    float4 b1v = __ldg(&((const float4*)bias)[sub * 2 + 1]);
    int deg = g_cnt[node];
    deg = (deg < CAP) ? deg : CAP;
    const int* sl = g_srcs + (size_t)node * CAP;
    const uint4* fth = (const uint4*)g_fth;   // 16B = 8 half channels per lane
    float accA[8] = {0.f, 0.f, 0.f, 0.f, 0.f, 0.f, 0.f, 0.f};
    float accB[8] = {0.f, 0.f, 0.f, 0.f, 0.f, 0.f, 0.f, 0.f};
    float s0 = 0.f, s1 = 0.f;
    int p = 0;
    for (; p + 2 <= deg; p += 2) {
        int2 ii = __ldg((const int2*)(sl + p));   // group-uniform 8B broadcast
        float e0 = __ldg(&g_el[ii.x * HH + h]) + erh;
        float e1 = __ldg(&g_el[ii.y * HH + h]) + erh;
        uint4 u0 = __ldg(&fth[(size_t)ii.x * 16 + sub]);
        uint4 u1 = __ldg(&fth[(size_t)ii.y * 16 + sub]);
        e0 = (e0 > 0.f) ? e0 : NEG * e0;
        e1 = (e1 > 0.f) ? e1 : NEG * e1;
        float x0 = __expf(e0), x1 = __expf(e1);
        float2 a0 = __half22float2(*(__half2*)&u0.x), a1 = __half22float2(*(__half2*)&u0.y);
        float2 a2 = __half22float2(*(__half2*)&u0.z), a3 = __half22float2(*(__half2*)&u0.w);
        float2 b0 = __half22float2(*(__half2*)&u1.x), b1 = __half22float2(*(__half2*)&u1.y);
        float2 b2 = __half22float2(*(__half2*)&u1.z), b3 = __half22float2(*(__half2*)&u1.w);
        accA[0] = fmaf(x0, a0.x, accA[0]); accA[1] = fmaf(x0, a0.y, accA[1]);
        accA[2] = fmaf(x0, a1.x, accA[2]); accA[3] = fmaf(x0, a1.y, accA[3]);
        accA[4] = fmaf(x0, a2.x, accA[4]); accA[5] = fmaf(x0, a2.y, accA[5]);
        accA[6] = fmaf(x0, a3.x, accA[6]); accA[7] = fmaf(x0, a3.y, accA[7]);
        accB[0] = fmaf(x1, b0.x, accB[0]); accB[1] = fmaf(x1, b0.y, accB[1]);
        accB[2] = fmaf(x1, b1.x, accB[2]); accB[3] = fmaf(x1, b1.y, accB[3]);
        accB[4] = fmaf(x1, b2.x, accB[4]); accB[5] = fmaf(x1, b2.y, accB[5]);
        accB[6] = fmaf(x1, b3.x, accB[6]); accB[7] = fmaf(x1, b3.y, accB[7]);
        s0 += x0; s1 += x1;
    }
    if (p < deg) {
        int i0 = __ldg(&sl[p]);
        float e0 = __ldg(&g_el[i0 * HH + h]) + erh;
        uint4 u0 = __ldg(&fth[(size_t)i0 * 16 + sub]);
        e0 = (e0 > 0.f) ? e0 : NEG * e0;
        float x0 = __expf(e0);
        float2 a0 = __half22float2(*(__half2*)&u0.x), a1 = __half22float2(*(__half2*)&u0.y);
        float2 a2 = __half22float2(*(__half2*)&u0.z), a3 = __half22float2(*(__half2*)&u0.w);
        accA[0] = fmaf(x0, a0.x, accA[0]); accA[1] = fmaf(x0, a0.y, accA[1]);
        accA[2] = fmaf(x0, a1.x, accA[2]); accA[3] = fmaf(x0, a1.y, accA[3]);
        accA[4] = fmaf(x0, a2.x, accA[4]); accA[5] = fmaf(x0, a2.y, accA[5]);
        accA[6] = fmaf(x0, a3.x, accA[6]); accA[7] = fmaf(x0, a3.y, accA[7]);
        s0 += x0;
    }
    float s = s0 + s1;
    float inv = 1.f / fmaxf(s, 1e-38f);
    float4 o0, o1;
    o0.x = fmaf(accA[0] + accB[0], inv, b0v.x);
    o0.y = fmaf(accA[1] + accB[1], inv, b0v.y);
    o0.z = fmaf(accA[2] + accB[2], inv, b0v.z);
    o0.w = fmaf(accA[3] + accB[3], inv, b0v.w);
    o1.x = fmaf(accA[4] + accB[4], inv, b1v.x);
    o1.y = fmaf(accA[5] + accB[5], inv, b1v.y);
    o1.z = fmaf(accA[6] + accB[6], inv, b1v.z);
    o1.w = fmaf(accA[7] + accB[7], inv, b1v.w);
    float4* out4 = (float4*)out;
    out4[(size_t)node * 32 + sub * 2] = o0;
    out4[(size_t)node * 32 + sub * 2 + 1] = o1;
}

// ---------------- launch ----------------
extern "C" void kernel_launch(void* const* d_in, const int* in_sizes, int n_in,
                              void* d_out, int out_size) {
    const float* feat   = (const float*)d_in[0];
    const void*  src    = d_in[1];
    const void*  dst    = d_in[2];
    const float* W      = (const float*)d_in[3];
    const float* attn_l = (const float*)d_in[4];
    const float* attn_r = (const float*)d_in[5];
    const float* bias   = (const float*)d_in[6];
    float* out = (float*)d_out;

    k_init<<<(N_ + 255) / 256, 256>>>(dst);
    k_scatter<<<(E_ / 2 + 255) / 256, 256>>>(src, dst);
    k_gemm_tc<<<(N_ + 127) / 128, 256>>>(feat, W, attn_l, attn_r);
    k_agg<<<(N_ * 16 + 255) / 256, 256>>>(bias, out);
}

// round 12
// speedup vs baseline: 1.3011x; 1.3011x over previous
#include <cuda_runtime.h>
#include <cuda_fp16.h>

// Problem constants
#define N_  100000
#define E_  1600000
#define DIN 128
#define HH  4
#define DD  32
#define HD  128        // HH*DD
#define NEG 0.2f
#define CAP 96         // per-node bucket capacity (Poisson(16) tail @96 ~ 1e-50)

// ---------------- device scratch (no allocations allowed) ----------------
__device__ __half g_fth[(size_t)N_ * HD];   // projected features fp16 (agg gather table)
__device__ float  g_el[N_ * HH];
__device__ float  g_er[N_ * HH];
__device__ int    g_cnt[N_];
__device__ int    g_srcs[(size_t)N_ * CAP]; // src ids bucketed by dst
__device__ int    g_is64;

// ---------------- dtype detect (int32 vs int64) + zero counters ----------
__global__ void k_init(const void* dst) {
    int i = blockIdx.x * blockDim.x + threadIdx.x;
    if (i < N_) g_cnt[i] = 0;
    if (i == 0) {
        const int* p = (const int*)dst;
        int odd_or = 0;
        // If data is int64 (values < 2^31), every odd 32-bit word is 0.
        #pragma unroll 1
        for (int j = 1; j < 64; j += 2) odd_or |= p[j];
        g_is64 = (odd_or == 0) ? 1 : 0;
    }
}

__device__ __forceinline__ int ld_idx(const void* p, int i, int is64) {
    return is64 ? (int)((const long long*)p)[i] : ((const int*)p)[i];
}

// ---------------- bucket scatter (no histogram/scan needed) ----------------
__global__ void k_scatter(const void* __restrict__ src, const void* __restrict__ dst) {
    int base = (blockIdx.x * blockDim.x + threadIdx.x) * 2;
    int is64 = g_is64;
    #pragma unroll
    for (int q = 0; q < 2; q++) {
        int i = base + q;
        if (i >= E_) return;
        int s = ld_idx(src, i, is64);
        int d = ld_idx(dst, i, is64);
        int p = atomicAdd(&g_cnt[d], 1);
        if (p < CAP) g_srcs[(size_t)d * CAP + p] = s;
    }
}

// ---------------- Tensor-core GEMM + fused attn epilogue (R9 version) -------
// ft[m][n] = sum_k feat[m][k] * W[n][k]; emits fp16 table + el/er directly.
// Block: 128M x 128N, 256 threads = 8 warps (4M x 2N), warp tile 32M x 64N.
// Inline 3xTF32 split (TK=32): D = ah*bh + al*bh + ah*bl; the cvt/sub work
// is hidden under MMA latency (hoisting it to smem regressed — R11 post-mortem).

__device__ __forceinline__ unsigned f2tf32(float x) {
    unsigned r;
    asm("cvt.rna.tf32.f32 %0, %1;" : "=r"(r) : "f"(x));
    return r;
}

__device__ __forceinline__ void mma_tf32(float* c,
                                         unsigned a0, unsigned a1, unsigned a2, unsigned a3,
                                         unsigned b0, unsigned b1) {
    asm volatile("mma.sync.aligned.m16n8k8.row.col.f32.tf32.tf32.f32 "
        "{%0,%1,%2,%3}, {%4,%5,%6,%7}, {%8,%9}, {%0,%1,%2,%3};"
        : "+f"(c[0]), "+f"(c[1]), "+f"(c[2]), "+f"(c[3])
        : "r"(a0), "r"(a1), "r"(a2), "r"(a3), "r"(b0), "r"(b1));
}

__global__ void __launch_bounds__(256) k_gemm_tc(const float* __restrict__ A,
                                                 const float* __restrict__ B,
                                                 const float* __restrict__ atl,
                                                 const float* __restrict__ atr) {
    __shared__ float As[32][132];   // As[k][m]
    __shared__ float Bs[32][132];   // Bs[k][n]  (= W[n][k])
    __shared__ float sel[128][4];
    __shared__ float ser[128][4];
    int tid = threadIdx.x;
    int lane = tid & 31;
    int warp = tid >> 5;
    int m0b = blockIdx.x * 128;
    int wm = (warp >> 1) * 32;      // warp M offset in block
    int wn = (warp & 1) * 64;       // warp N offset in block

    // zero el/er accumulators
    #pragma unroll
    for (int idx = tid; idx < 512; idx += 256) {
        sel[idx >> 2][idx & 3] = 0.f;
        ser[idx >> 2][idx & 3] = 0.f;
    }

    float c_[2][8][4];
    #pragma unroll
    for (int i = 0; i < 2; i++)
        #pragma unroll
        for (int j = 0; j < 8; j++)
            #pragma unroll
            for (int q = 0; q < 4; q++) c_[i][j][q] = 0.f;

    for (int kt = 0; kt < DIN; kt += 32) {
        #pragma unroll
        for (int l = 0; l < 4; l++) {
            int idx = tid + l * 256;       // 0..1023
            int r = idx >> 3, c4 = idx & 7;
            int gm = m0b + r;
            float4 va = make_float4(0.f, 0.f, 0.f, 0.f);
            if (gm < N_) va = *(const float4*)(A + (size_t)gm * DIN + kt + c4 * 4);
            As[c4 * 4 + 0][r] = va.x; As[c4 * 4 + 1][r] = va.y;
            As[c4 * 4 + 2][r] = va.z; As[c4 * 4 + 3][r] = va.w;
            float4 vb = *(const float4*)(B + (size_t)r * DIN + kt + c4 * 4);
            Bs[c4 * 4 + 0][r] = vb.x; Bs[c4 * 4 + 1][r] = vb.y;
            Bs[c4 * 4 + 2][r] = vb.z; Bs[c4 * 4 + 3][r] = vb.w;
        }
        __syncthreads();
        #pragma unroll
        for (int ks = 0; ks < 32; ks += 8) {
            unsigned ah[2][4], al_[2][4];
            #pragma unroll
            for (int i = 0; i < 2; i++) {
                int r = wm + i * 16 + (lane >> 2);
                int kk = ks + (lane & 3);
                float x0 = As[kk][r];
                float x1 = As[kk][r + 8];
                float x2 = As[kk + 4][r];
                float x3 = As[kk + 4][r + 8];
                ah[i][0] = f2tf32(x0); al_[i][0] = f2tf32(x0 - __uint_as_float(ah[i][0]));
                ah[i][1] = f2tf32(x1); al_[i][1] = f2tf32(x1 - __uint_as_float(ah[i][1]));
                ah[i][2] = f2tf32(x2); al_[i][2] = f2tf32(x2 - __uint_as_float(ah[i][2]));
                ah[i][3] = f2tf32(x3); al_[i][3] = f2tf32(x3 - __uint_as_float(ah[i][3]));
            }
            #pragma unroll
            for (int j = 0; j < 8; j++) {
                int cn = wn + j * 8 + (lane >> 2);
                int kk = ks + (lane & 3);
                float y0 = Bs[kk][cn];
                float y1 = Bs[kk + 4][cn];
                unsigned bh0 = f2tf32(y0);
                unsigned bh1 = f2tf32(y1);
                unsigned bl0 = f2tf32(y0 - __uint_as_float(bh0));
                unsigned bl1 = f2tf32(y1 - __uint_as_float(bh1));
                #pragma unroll
                for (int i = 0; i < 2; i++) {
                    mma_tf32(c_[i][j], ah[i][0], ah[i][1], ah[i][2], ah[i][3], bh0, bh1);
                    mma_tf32(c_[i][j], al_[i][0], al_[i][1], al_[i][2], al_[i][3], bh0, bh1);
                    mma_tf32(c_[i][j], ah[i][0], ah[i][1], ah[i][2], ah[i][3], bl0, bl1);
                }
            }
        }
        __syncthreads();
    }

    // ---- epilogue: store fp16 ft, accumulate el/er into smem ----
    int h0w = wn >> 5;                // first head covered by this warp (j=0..3)
    #pragma unroll
    for (int i = 0; i < 2; i++) {
        int rloc0 = wm + i * 16 + (lane >> 2);  // local row (0..127)
        int r0 = m0b + rloc0;
        float el_a = 0.f, er_a = 0.f, el_b = 0.f, er_b = 0.f;   // row r0: head h0w, h0w+1
        float el_c = 0.f, er_c = 0.f, el_d = 0.f, er_d = 0.f;   // row r0+8
        #pragma unroll
        for (int j = 0; j < 8; j++) {
            int cn = wn + j * 8 + 2 * (lane & 3);
            float a0 = __ldg(&atl[cn]),     a1 = __ldg(&atl[cn + 1]);
            float b0 = __ldg(&atr[cn]),     b1 = __ldg(&atr[cn + 1]);
            float c0 = c_[i][j][0], c1 = c_[i][j][1];
            float c2 = c_[i][j][2], c3 = c_[i][j][3];
            if (j < 4) {
                el_a += c0 * a0 + c1 * a1;  er_a += c0 * b0 + c1 * b1;
                el_c += c2 * a0 + c3 * a1;  er_c += c2 * b0 + c3 * b1;
            } else {
                el_b += c0 * a0 + c1 * a1;  er_b += c0 * b0 + c1 * b1;
                el_d += c2 * a0 + c3 * a1;  er_d += c2 * b0 + c3 * b1;
            }
            if (r0 < N_)
                *(__half2*)&g_fth[(size_t)r0 * HD + cn] = __floats2half2_rn(c0, c1);
            if (r0 + 8 < N_)
                *(__half2*)&g_fth[(size_t)(r0 + 8) * HD + cn] = __floats2half2_rn(c2, c3);
        }
        atomicAdd(&sel[rloc0][h0w], el_a);     atomicAdd(&ser[rloc0][h0w], er_a);
        atomicAdd(&sel[rloc0][h0w + 1], el_b); atomicAdd(&ser[rloc0][h0w + 1], er_b);
        atomicAdd(&sel[rloc0 + 8][h0w], el_c);     atomicAdd(&ser[rloc0 + 8][h0w], er_c);
        atomicAdd(&sel[rloc0 + 8][h0w + 1], el_d); atomicAdd(&ser[rloc0 + 8][h0w + 1], er_d);
    }
    __syncthreads();
    #pragma unroll
    for (int idx = tid; idx < 512; idx += 256) {
        int r = idx >> 2, h = idx & 3;
        int gm = m0b + r;
        if (gm < N_) {
            g_el[gm * HH + h] = sel[r][h];
            g_er[gm * HH + h] = ser[r][h];
        }
    }
}

// ---------------- fused softmax + aggregation (R11 version, measured 69.3us) -
// 16 lanes per dst node (2 nodes per warp), 8 channels per lane (uint4 = 16B
// gather). MLP=2 edges in flight: same in-flight bytes as a 32-lane MLP=4
// scheme but ~35% fewer warp instructions (kernel is issue-bound).
// rst = (sum_i ex_i * ft16[src_i]) / sum_i ex_i + bias  (max-free softmax)
__global__ void k_agg(const float* __restrict__ bias, float* __restrict__ out) {
    int node = (blockIdx.x * blockDim.x + threadIdx.x) >> 4;
    if (node >= N_) return;
    int sub = threadIdx.x & 15;      // lane within node group
    int h = sub >> 2;                // head (4 lanes per head, 8 ch each)
    // loop-independent loads issued up front
    float erh = __ldg(&g_er[node * HH + h]);
    float4 b0v = __ldg(&((const float4*)bias)[sub * 2]);
    float4 b1v = __ldg(&((const float4*)bias)[sub * 2 + 1]);
    int deg = g_cnt[node];
    deg = (deg < CAP) ? deg : CAP;
    const int* sl = g_srcs + (size_t)node * CAP;
    const uint4* fth = (const uint4*)g_fth;   // 16B = 8 half channels per lane
    float accA[8] = {0.f, 0.f, 0.f, 0.f, 0.f, 0.f, 0.f, 0.f};
    float accB[8] = {0.f, 0.f, 0.f, 0.f, 0.f, 0.f, 0.f, 0.f};
    float s0 = 0.f, s1 = 0.f;
    int p = 0;
    for (; p + 2 <= deg; p += 2) {
        int2 ii = __ldg((const int2*)(sl + p));   // group-uniform 8B broadcast
        float e0 = __ldg(&g_el[ii.x * HH + h]) + erh;
        float e1 = __ldg(&g_el[ii.y * HH + h]) + erh;
        uint4 u0 = __ldg(&fth[(size_t)ii.x * 16 + sub]);
        uint4 u1 = __ldg(&fth[(size_t)ii.y * 16 + sub]);
        e0 = (e0 > 0.f) ? e0 : NEG * e0;
        e1 = (e1 > 0.f) ? e1 : NEG * e1;
        float x0 = __expf(e0), x1 = __expf(e1);
        float2 a0 = __half22float2(*(__half2*)&u0.x), a1 = __half22float2(*(__half2*)&u0.y);
        float2 a2 = __half22float2(*(__half2*)&u0.z), a3 = __half22float2(*(__half2*)&u0.w);
        float2 b0 = __half22float2(*(__half2*)&u1.x), b1 = __half22float2(*(__half2*)&u1.y);
        float2 b2 = __half22float2(*(__half2*)&u1.z), b3 = __half22float2(*(__half2*)&u1.w);
        accA[0] = fmaf(x0, a0.x, accA[0]); accA[1] = fmaf(x0, a0.y, accA[1]);
        accA[2] = fmaf(x0, a1.x, accA[2]); accA[3] = fmaf(x0, a1.y, accA[3]);
        accA[4] = fmaf(x0, a2.x, accA[4]); accA[5] = fmaf(x0, a2.y, accA[5]);
        accA[6] = fmaf(x0, a3.x, accA[6]); accA[7] = fmaf(x0, a3.y, accA[7]);
        accB[0] = fmaf(x1, b0.x, accB[0]); accB[1] = fmaf(x1, b0.y, accB[1]);
        accB[2] = fmaf(x1, b1.x, accB[2]); accB[3] = fmaf(x1, b1.y, accB[3]);
        accB[4] = fmaf(x1, b2.x, accB[4]); accB[5] = fmaf(x1, b2.y, accB[5]);
        accB[6] = fmaf(x1, b3.x, accB[6]); accB[7] = fmaf(x1, b3.y, accB[7]);
        s0 += x0; s1 += x1;
    }
    if (p < deg) {
        int i0 = __ldg(&sl[p]);
        float e0 = __ldg(&g_el[i0 * HH + h]) + erh;
        uint4 u0 = __ldg(&fth[(size_t)i0 * 16 + sub]);
        e0 = (e0 > 0.f) ? e0 : NEG * e0;
        float x0 = __expf(e0);
        float2 a0 = __half22float2(*(__half2*)&u0.x), a1 = __half22float2(*(__half2*)&u0.y);
        float2 a2 = __half22float2(*(__half2*)&u0.z), a3 = __half22float2(*(__half2*)&u0.w);
        accA[0] = fmaf(x0, a0.x, accA[0]); accA[1] = fmaf(x0, a0.y, accA[1]);
        accA[2] = fmaf(x0, a1.x, accA[2]); accA[3] = fmaf(x0, a1.y, accA[3]);
        accA[4] = fmaf(x0, a2.x, accA[4]); accA[5] = fmaf(x0, a2.y, accA[5]);
        accA[6] = fmaf(x0, a3.x, accA[6]); accA[7] = fmaf(x0, a3.y, accA[7]);
        s0 += x0;
    }
    float s = s0 + s1;
    float inv = 1.f / fmaxf(s, 1e-38f);
    float4 o0, o1;
    o0.x = fmaf(accA[0] + accB[0], inv, b0v.x);
    o0.y = fmaf(accA[1] + accB[1], inv, b0v.y);
    o0.z = fmaf(accA[2] + accB[2], inv, b0v.z);
    o0.w = fmaf(accA[3] + accB[3], inv, b0v.w);
    o1.x = fmaf(accA[4] + accB[4], inv, b1v.x);
    o1.y = fmaf(accA[5] + accB[5], inv, b1v.y);
    o1.z = fmaf(accA[6] + accB[6], inv, b1v.z);
    o1.w = fmaf(accA[7] + accB[7], inv, b1v.w);
    float4* out4 = (float4*)out;
    out4[(size_t)node * 32 + sub * 2] = o0;
    out4[(size_t)node * 32 + sub * 2 + 1] = o1;
}

// ---------------- launch ----------------
extern "C" void kernel_launch(void* const* d_in, const int* in_sizes, int n_in,
                              void* d_out, int out_size) {
    const float* feat   = (const float*)d_in[0];
    const void*  src    = d_in[1];
    const void*  dst    = d_in[2];
    const float* W      = (const float*)d_in[3];
    const float* attn_l = (const float*)d_in[4];
    const float* attn_r = (const float*)d_in[5];
    const float* bias   = (const float*)d_in[6];
    float* out = (float*)d_out;

    k_init<<<(N_ + 255) / 256, 256>>>(dst);
    k_scatter<<<(E_ / 2 + 255) / 256, 256>>>(src, dst);
    k_gemm_tc<<<(N_ + 127) / 128, 256>>>(feat, W, attn_l, attn_r);
    k_agg<<<(N_ * 16 + 255) / 256, 256>>>(bias, out);
}

// round 13
// speedup vs baseline: 1.4303x; 1.0993x over previous
#include <cuda_runtime.h>
#include <cuda_fp16.h>

// Problem constants
#define N_  100000
#define E_  1600000
#define DIN 128
#define HH  4
#define DD  32
#define HD  128        // HH*DD
#define NEG 0.2f
#define CAP 96         // per-node bucket capacity (Poisson(16) tail @96 ~ 1e-50)

// ---------------- device scratch (no allocations allowed) ----------------
__device__ __half g_fth[(size_t)N_ * HD];   // projected features fp16 (agg gather table)
__device__ float  g_el[N_ * HH];
__device__ float  g_er[N_ * HH];
__device__ int    g_cnt[N_];
__device__ int    g_srcs[(size_t)N_ * CAP]; // src ids bucketed by dst
__device__ int    g_is64;

// ---------------- dtype detect (int32 vs int64) + zero counters ----------
__global__ void k_init(const void* dst) {
    int i = blockIdx.x * blockDim.x + threadIdx.x;
    if (i < N_) g_cnt[i] = 0;
    if (i == 0) {
        const int* p = (const int*)dst;
        int odd_or = 0;
        // If data is int64 (values < 2^31), every odd 32-bit word is 0.
        #pragma unroll 1
        for (int j = 1; j < 64; j += 2) odd_or |= p[j];
        g_is64 = (odd_or == 0) ? 1 : 0;
    }
}

__device__ __forceinline__ int ld_idx(const void* p, int i, int is64) {
    return is64 ? (int)((const long long*)p)[i] : ((const int*)p)[i];
}

// ---------------- bucket scatter (no histogram/scan needed) ----------------
__global__ void k_scatter(const void* __restrict__ src, const void* __restrict__ dst) {
    int base = (blockIdx.x * blockDim.x + threadIdx.x) * 2;
    int is64 = g_is64;
    #pragma unroll
    for (int q = 0; q < 2; q++) {
        int i = base + q;
        if (i >= E_) return;
        int s = ld_idx(src, i, is64);
        int d = ld_idx(dst, i, is64);
        int p = atomicAdd(&g_cnt[d], 1);
        if (p < CAP) g_srcs[(size_t)d * CAP + p] = s;
    }
}

// ---------------- Tensor-core GEMM + fused attn epilogue ----------
// ft[m][n] = sum_k feat[m][k] * W[n][k]; emits fp16 table + el/er directly.
// Block: 128M x 128N, 256 threads = 8 warps (4M x 2N), warp tile 32M x 64N.
// 2xTF32 split: A = ah + al (both tf32), B = bh only.
//   D = ah*bh + al*bh  (omitted A*bl term ~2.8e-4 RMS relative — within the
//   1e-3 gate alongside the fp16 message quantization; saves 1/3 of MMA work.)

__device__ __forceinline__ unsigned f2tf32(float x) {
    unsigned r;
    asm("cvt.rna.tf32.f32 %0, %1;" : "=r"(r) : "f"(x));
    return r;
}

__device__ __forceinline__ void mma_tf32(float* c,
                                         unsigned a0, unsigned a1, unsigned a2, unsigned a3,
                                         unsigned b0, unsigned b1) {
    asm volatile("mma.sync.aligned.m16n8k8.row.col.f32.tf32.tf32.f32 "
        "{%0,%1,%2,%3}, {%4,%5,%6,%7}, {%8,%9}, {%0,%1,%2,%3};"
        : "+f"(c[0]), "+f"(c[1]), "+f"(c[2]), "+f"(c[3])
        : "r"(a0), "r"(a1), "r"(a2), "r"(a3), "r"(b0), "r"(b1));
}

__global__ void __launch_bounds__(256) k_gemm_tc(const float* __restrict__ A,
                                                 const float* __restrict__ B,
                                                 const float* __restrict__ atl,
                                                 const float* __restrict__ atr) {
    __shared__ float As[32][132];   // As[k][m]
    __shared__ float Bs[32][132];   // Bs[k][n]  (= W[n][k])
    __shared__ float sel[128][4];
    __shared__ float ser[128][4];
    int tid = threadIdx.x;
    int lane = tid & 31;
    int warp = tid >> 5;
    int m0b = blockIdx.x * 128;
    int wm = (warp >> 1) * 32;      // warp M offset in block
    int wn = (warp & 1) * 64;       // warp N offset in block

    // zero el/er accumulators
    #pragma unroll
    for (int idx = tid; idx < 512; idx += 256) {
        sel[idx >> 2][idx & 3] = 0.f;
        ser[idx >> 2][idx & 3] = 0.f;
    }

    float c_[2][8][4];
    #pragma unroll
    for (int i = 0; i < 2; i++)
        #pragma unroll
        for (int j = 0; j < 8; j++)
            #pragma unroll
            for (int q = 0; q < 4; q++) c_[i][j][q] = 0.f;

    for (int kt = 0; kt < DIN; kt += 32) {
        #pragma unroll
        for (int l = 0; l < 4; l++) {
            int idx = tid + l * 256;       // 0..1023
            int r = idx >> 3, c4 = idx & 7;
            int gm = m0b + r;
            float4 va = make_float4(0.f, 0.f, 0.f, 0.f);
            if (gm < N_) va = *(const float4*)(A + (size_t)gm * DIN + kt + c4 * 4);
            As[c4 * 4 + 0][r] = va.x; As[c4 * 4 + 1][r] = va.y;
            As[c4 * 4 + 2][r] = va.z; As[c4 * 4 + 3][r] = va.w;
            float4 vb = *(const float4*)(B + (size_t)r * DIN + kt + c4 * 4);
            Bs[c4 * 4 + 0][r] = vb.x; Bs[c4 * 4 + 1][r] = vb.y;
            Bs[c4 * 4 + 2][r] = vb.z; Bs[c4 * 4 + 3][r] = vb.w;
        }
        __syncthreads();
        #pragma unroll
        for (int ks = 0; ks < 32; ks += 8) {
            unsigned ah[2][4], al_[2][4];
            #pragma unroll
            for (int i = 0; i < 2; i++) {
                int r = wm + i * 16 + (lane >> 2);
                int kk = ks + (lane & 3);
                float x0 = As[kk][r];
                float x1 = As[kk][r + 8];
                float x2 = As[kk + 4][r];
                float x3 = As[kk + 4][r + 8];
                ah[i][0] = f2tf32(x0); al_[i][0] = f2tf32(x0 - __uint_as_float(ah[i][0]));
                ah[i][1] = f2tf32(x1); al_[i][1] = f2tf32(x1 - __uint_as_float(ah[i][1]));
                ah[i][2] = f2tf32(x2); al_[i][2] = f2tf32(x2 - __uint_as_float(ah[i][2]));
                ah[i][3] = f2tf32(x3); al_[i][3] = f2tf32(x3 - __uint_as_float(ah[i][3]));
            }
            #pragma unroll
            for (int j = 0; j < 8; j++) {
                int cn = wn + j * 8 + (lane >> 2);
                int kk = ks + (lane & 3);
                unsigned bh0 = f2tf32(Bs[kk][cn]);
                unsigned bh1 = f2tf32(Bs[kk + 4][cn]);
                #pragma unroll
                for (int i = 0; i < 2; i++) {
                    mma_tf32(c_[i][j], ah[i][0], ah[i][1], ah[i][2], ah[i][3], bh0, bh1);
                    mma_tf32(c_[i][j], al_[i][0], al_[i][1], al_[i][2], al_[i][3], bh0, bh1);
                }
            }
        }
        __syncthreads();
    }

    // ---- epilogue: store fp16 ft, accumulate el/er into smem ----
    int h0w = wn >> 5;                // first head covered by this warp (j=0..3)
    #pragma unroll
    for (int i = 0; i < 2; i++) {
        int rloc0 = wm + i * 16 + (lane >> 2);  // local row (0..127)
        int r0 = m0b + rloc0;
        float el_a = 0.f, er_a = 0.f, el_b = 0.f, er_b = 0.f;   // row r0: head h0w, h0w+1
        float el_c = 0.f, er_c = 0.f, el_d = 0.f, er_d = 0.f;   // row r0+8
        #pragma unroll
        for (int j = 0; j < 8; j++) {
            int cn = wn + j * 8 + 2 * (lane & 3);
            float a0 = __ldg(&atl[cn]),     a1 = __ldg(&atl[cn + 1]);
            float b0 = __ldg(&atr[cn]),     b1 = __ldg(&atr[cn + 1]);
            float c0 = c_[i][j][0], c1 = c_[i][j][1];
            float c2 = c_[i][j][2], c3 = c_[i][j][3];
            if (j < 4) {
                el_a += c0 * a0 + c1 * a1;  er_a += c0 * b0 + c1 * b1;
                el_c += c2 * a0 + c3 * a1;  er_c += c2 * b0 + c3 * b1;
            } else {
                el_b += c0 * a0 + c1 * a1;  er_b += c0 * b0 + c1 * b1;
                el_d += c2 * a0 + c3 * a1;  er_d += c2 * b0 + c3 * b1;
            }
            if (r0 < N_)
                *(__half2*)&g_fth[(size_t)r0 * HD + cn] = __floats2half2_rn(c0, c1);
            if (r0 + 8 < N_)
                *(__half2*)&g_fth[(size_t)(r0 + 8) * HD + cn] = __floats2half2_rn(c2, c3);
        }
        atomicAdd(&sel[rloc0][h0w], el_a);     atomicAdd(&ser[rloc0][h0w], er_a);
        atomicAdd(&sel[rloc0][h0w + 1], el_b); atomicAdd(&ser[rloc0][h0w + 1], er_b);
        atomicAdd(&sel[rloc0 + 8][h0w], el_c);     atomicAdd(&ser[rloc0 + 8][h0w], er_c);
        atomicAdd(&sel[rloc0 + 8][h0w + 1], el_d); atomicAdd(&ser[rloc0 + 8][h0w + 1], er_d);
    }
    __syncthreads();
    #pragma unroll
    for (int idx = tid; idx < 512; idx += 256) {
        int r = idx >> 2, h = idx & 3;
        int gm = m0b + r;
        if (gm < N_) {
            g_el[gm * HH + h] = sel[r][h];
            g_er[gm * HH + h] = ser[r][h];
        }
    }
}

// ---------------- fused softmax + aggregation (measured 69.3us) -------------
// 16 lanes per dst node (2 nodes per warp), 8 channels per lane (uint4 = 16B
// gather). MLP=2 edges in flight; issue-thinned (kernel is issue-bound).
// rst = (sum_i ex_i * ft16[src_i]) / sum_i ex_i + bias  (max-free softmax)
__global__ void k_agg(const float* __restrict__ bias, float* __restrict__ out) {
    int node = (blockIdx.x * blockDim.x + threadIdx.x) >> 4;
    if (node >= N_) return;
    int sub = threadIdx.x & 15;      // lane within node group
    int h = sub >> 2;                // head (4 lanes per head, 8 ch each)
    // loop-independent loads issued up front
    float erh = __ldg(&g_er[node * HH + h]);
    float4 b0v = __ldg(&((const float4*)bias)[sub * 2]);
    float4 b1v = __ldg(&((const float4*)bias)[sub * 2 + 1]);
    int deg = g_cnt[node];
    deg = (deg < CAP) ? deg : CAP;
    const int* sl = g_srcs + (size_t)node * CAP;
    const uint4* fth = (const uint4*)g_fth;   // 16B = 8 half channels per lane
    float accA[8] = {0.f, 0.f, 0.f, 0.f, 0.f, 0.f, 0.f, 0.f};
    float accB[8] = {0.f, 0.f, 0.f, 0.f, 0.f, 0.f, 0.f, 0.f};
    float s0 = 0.f, s1 = 0.f;
    int p = 0;
    for (; p + 2 <= deg; p += 2) {
        int2 ii = __ldg((const int2*)(sl + p));   // group-uniform 8B broadcast
        float e0 = __ldg(&g_el[ii.x * HH + h]) + erh;
        float e1 = __ldg(&g_el[ii.y * HH + h]) + erh;
        uint4 u0 = __ldg(&fth[(size_t)ii.x * 16 + sub]);
        uint4 u1 = __ldg(&fth[(size_t)ii.y * 16 + sub]);
        e0 = (e0 > 0.f) ? e0 : NEG * e0;
        e1 = (e1 > 0.f) ? e1 : NEG * e1;
        float x0 = __expf(e0), x1 = __expf(e1);
        float2 a0 = __half22float2(*(__half2*)&u0.x), a1 = __half22float2(*(__half2*)&u0.y);
        float2 a2 = __half22float2(*(__half2*)&u0.z), a3 = __half22float2(*(__half2*)&u0.w);
        float2 b0 = __half22float2(*(__half2*)&u1.x), b1 = __half22float2(*(__half2*)&u1.y);
        float2 b2 = __half22float2(*(__half2*)&u1.z), b3 = __half22float2(*(__half2*)&u1.w);
        accA[0] = fmaf(x0, a0.x, accA[0]); accA[1] = fmaf(x0, a0.y, accA[1]);
        accA[2] = fmaf(x0, a1.x, accA[2]); accA[3] = fmaf(x0, a1.y, accA[3]);
        accA[4] = fmaf(x0, a2.x, accA[4]); accA[5] = fmaf(x0, a2.y, accA[5]);
        accA[6] = fmaf(x0, a3.x, accA[6]); accA[7] = fmaf(x0, a3.y, accA[7]);
        accB[0] = fmaf(x1, b0.x, accB[0]); accB[1] = fmaf(x1, b0.y, accB[1]);
        accB[2] = fmaf(x1, b1.x, accB[2]); accB[3] = fmaf(x1, b1.y, accB[3]);
        accB[4] = fmaf(x1, b2.x, accB[4]); accB[5] = fmaf(x1, b2.y, accB[5]);
        accB[6] = fmaf(x1, b3.x, accB[6]); accB[7] = fmaf(x1, b3.y, accB[7]);
        s0 += x0; s1 += x1;
    }
    if (p < deg) {
        int i0 = __ldg(&sl[p]);
        float e0 = __ldg(&g_el[i0 * HH + h]) + erh;
        uint4 u0 = __ldg(&fth[(size_t)i0 * 16 + sub]);
        e0 = (e0 > 0.f) ? e0 : NEG * e0;
        float x0 = __expf(e0);
        float2 a0 = __half22float2(*(__half2*)&u0.x), a1 = __half22float2(*(__half2*)&u0.y);
        float2 a2 = __half22float2(*(__half2*)&u0.z), a3 = __half22float2(*(__half2*)&u0.w);
        accA[0] = fmaf(x0, a0.x, accA[0]); accA[1] = fmaf(x0, a0.y, accA[1]);
        accA[2] = fmaf(x0, a1.x, accA[2]); accA[3] = fmaf(x0, a1.y, accA[3]);
        accA[4] = fmaf(x0, a2.x, accA[4]); accA[5] = fmaf(x0, a2.y, accA[5]);
        accA[6] = fmaf(x0, a3.x, accA[6]); accA[7] = fmaf(x0, a3.y, accA[7]);
        s0 += x0;
    }
    float s = s0 + s1;
    float inv = 1.f / fmaxf(s, 1e-38f);
    float4 o0, o1;
    o0.x = fmaf(accA[0] + accB[0], inv, b0v.x);
    o0.y = fmaf(accA[1] + accB[1], inv, b0v.y);
    o0.z = fmaf(accA[2] + accB[2], inv, b0v.z);
    o0.w = fmaf(accA[3] + accB[3], inv, b0v.w);
    o1.x = fmaf(accA[4] + accB[4], inv, b1v.x);
    o1.y = fmaf(accA[5] + accB[5], inv, b1v.y);
    o1.z = fmaf(accA[6] + accB[6], inv, b1v.z);
    o1.w = fmaf(accA[7] + accB[7], inv, b1v.w);
    float4* out4 = (float4*)out;
    out4[(size_t)node * 32 + sub * 2] = o0;
    out4[(size_t)node * 32 + sub * 2 + 1] = o1;
}

// ---------------- launch ----------------
extern "C" void kernel_launch(void* const* d_in, const int* in_sizes, int n_in,
                              void* d_out, int out_size) {
    const float* feat   = (const float*)d_in[0];
    const void*  src    = d_in[1];
    const void*  dst    = d_in[2];
    const float* W      = (const float*)d_in[3];
    const float* attn_l = (const float*)d_in[4];
    const float* attn_r = (const float*)d_in[5];
    const float* bias   = (const float*)d_in[6];
    float* out = (float*)d_out;

    k_init<<<(N_ + 255) / 256, 256>>>(dst);
    k_scatter<<<(E_ / 2 + 255) / 256, 256>>>(src, dst);
    k_gemm_tc<<<(N_ + 127) / 128, 256>>>(feat, W, attn_l, attn_r);
    k_agg<<<(N_ * 16 + 255) / 256, 256>>>(bias, out);
}

// round 15
// speedup vs baseline: 1.5197x; 1.0626x over previous
#include <cuda_runtime.h>
#include <cuda_fp16.h>

// Problem constants
#define N_  100000
#define E_  1600000
#define DIN 128
#define HH  4
#define DD  32
#define HD  128        // HH*DD
#define NEG 0.2f
#define CAP 96         // per-node bucket capacity (Poisson(16) tail @96 ~ 1e-50)

// ---------------- device scratch (no allocations allowed) ----------------
__device__ __half g_fth[(size_t)N_ * HD];   // projected features fp16 (agg gather table)
__device__ float  g_el[N_ * HH];
__device__ float  g_er[N_ * HH];
__device__ int    g_cnt[N_];
__device__ int    g_srcs[(size_t)N_ * CAP]; // src ids bucketed by dst
__device__ int    g_is64;

// ---------------- dtype detect (int32 vs int64) + zero counters ----------
__global__ void k_init(const void* dst) {
    int i = blockIdx.x * blockDim.x + threadIdx.x;
    if (i < N_) g_cnt[i] = 0;
    if (i == 0) {
        const int* p = (const int*)dst;
        int odd_or = 0;
        // If data is int64 (values < 2^31), every odd 32-bit word is 0.
        #pragma unroll 1
        for (int j = 1; j < 64; j += 2) odd_or |= p[j];
        g_is64 = (odd_or == 0) ? 1 : 0;
    }
}

__device__ __forceinline__ int ld_idx(const void* p, int i, int is64) {
    return is64 ? (int)((const long long*)p)[i] : ((const int*)p)[i];
}

// ---------------- bucket scatter (no histogram/scan needed) ----------------
__global__ void k_scatter(const void* __restrict__ src, const void* __restrict__ dst) {
    int base = (blockIdx.x * blockDim.x + threadIdx.x) * 2;
    int is64 = g_is64;
    #pragma unroll
    for (int q = 0; q < 2; q++) {
        int i = base + q;
        if (i >= E_) return;
        int s = ld_idx(src, i, is64);
        int d = ld_idx(dst, i, is64);
        int p = atomicAdd(&g_cnt[d], 1);
        if (p < CAP) g_srcs[(size_t)d * CAP + p] = s;
    }
}

// ---------------- Tensor-core GEMM + fused attn epilogue ----------
// ft[m][n] = sum_k feat[m][k] * W[n][k]; emits fp16 table + el/er directly.
// Block: 128M x 128N, 256 threads = 8 warps (4M x 2N), warp tile 32M x 64N.
// Pure 1xTF32: inputs rounded to tf32 ONCE at smem-store time (tf32 values are
// valid fp32 bit patterns, so smem layout is unchanged); mainloop is pure
// LDS + MMA. Rounding error ~3e-4 RMS relative — within the 1e-3 gate
// alongside the fp16 message quantization (error model calibrated R9→R13).

__device__ __forceinline__ float tf32r(float x) {
    unsigned r;
    asm("cvt.rna.tf32.f32 %0, %1;" : "=r"(r) : "f"(x));
    return __uint_as_float(r);
}

__device__ __forceinline__ void mma_tf32(float* c,
                                         unsigned a0, unsigned a1, unsigned a2, unsigned a3,
                                         unsigned b0, unsigned b1) {
    asm volatile("mma.sync.aligned.m16n8k8.row.col.f32.tf32.tf32.f32 "
        "{%0,%1,%2,%3}, {%4,%5,%6,%7}, {%8,%9}, {%0,%1,%2,%3};"
        : "+f"(c[0]), "+f"(c[1]), "+f"(c[2]), "+f"(c[3])
        : "r"(a0), "r"(a1), "r"(a2), "r"(a3), "r"(b0), "r"(b1));
}

__global__ void __launch_bounds__(256) k_gemm_tc(const float* __restrict__ A,
                                                 const float* __restrict__ B,
                                                 const float* __restrict__ atl,
                                                 const float* __restrict__ atr) {
    __shared__ float As[32][132];   // As[k][m], values pre-rounded to tf32
    __shared__ float Bs[32][132];   // Bs[k][n]  (= W[n][k]), pre-rounded
    __shared__ float sel[128][4];
    __shared__ float ser[128][4];
    int tid = threadIdx.x;
    int lane = tid & 31;
    int warp = tid >> 5;
    int m0b = blockIdx.x * 128;
    int wm = (warp >> 1) * 32;      // warp M offset in block
    int wn = (warp & 1) * 64;       // warp N offset in block

    // zero el/er accumulators
    #pragma unroll
    for (int idx = tid; idx < 512; idx += 256) {
        sel[idx >> 2][idx & 3] = 0.f;
        ser[idx >> 2][idx & 3] = 0.f;
    }

    float c_[2][8][4];
    #pragma unroll
    for (int i = 0; i < 2; i++)
        #pragma unroll
        for (int j = 0; j < 8; j++)
            #pragma unroll
            for (int q = 0; q < 4; q++) c_[i][j][q] = 0.f;

    for (int kt = 0; kt < DIN; kt += 32) {
        #pragma unroll
        for (int l = 0; l < 4; l++) {
            int idx = tid + l * 256;       // 0..1023
            int r = idx >> 3, c4 = idx & 7;
            int gm = m0b + r;
            float4 va = make_float4(0.f, 0.f, 0.f, 0.f);
            if (gm < N_) va = *(const float4*)(A + (size_t)gm * DIN + kt + c4 * 4);
            As[c4 * 4 + 0][r] = tf32r(va.x); As[c4 * 4 + 1][r] = tf32r(va.y);
            As[c4 * 4 + 2][r] = tf32r(va.z); As[c4 * 4 + 3][r] = tf32r(va.w);
            float4 vb = *(const float4*)(B + (size_t)r * DIN + kt + c4 * 4);
            Bs[c4 * 4 + 0][r] = tf32r(vb.x); Bs[c4 * 4 + 1][r] = tf32r(vb.y);
            Bs[c4 * 4 + 2][r] = tf32r(vb.z); Bs[c4 * 4 + 3][r] = tf32r(vb.w);
        }
        __syncthreads();
        #pragma unroll
        for (int ks = 0; ks < 32; ks += 8) {
            unsigned ah[2][4];
            #pragma unroll
            for (int i = 0; i < 2; i++) {
                int r = wm + i * 16 + (lane >> 2);
                int kk = ks + (lane & 3);
                ah[i][0] = __float_as_uint(As[kk][r]);
                ah[i][1] = __float_as_uint(As[kk][r + 8]);
                ah[i][2] = __float_as_uint(As[kk + 4][r]);
                ah[i][3] = __float_as_uint(As[kk + 4][r + 8]);
            }
            #pragma unroll
            for (int j = 0; j < 8; j++) {
                int cn = wn + j * 8 + (lane >> 2);
                int kk = ks + (lane & 3);
                unsigned bh0 = __float_as_uint(Bs[kk][cn]);
                unsigned bh1 = __float_as_uint(Bs[kk + 4][cn]);
                #pragma unroll
                for (int i = 0; i < 2; i++)
                    mma_tf32(c_[i][j], ah[i][0], ah[i][1], ah[i][2], ah[i][3], bh0, bh1);
            }
        }
        __syncthreads();
    }

    // ---- epilogue: store fp16 ft, accumulate el/er into smem ----
    int h0w = wn >> 5;                // first head covered by this warp (j=0..3)
    #pragma unroll
    for (int i = 0; i < 2; i++) {
        int rloc0 = wm + i * 16 + (lane >> 2);  // local row (0..127)
        int r0 = m0b + rloc0;
        float el_a = 0.f, er_a = 0.f, el_b = 0.f, er_b = 0.f;   // row r0: head h0w, h0w+1
        float el_c = 0.f, er_c = 0.f, el_d = 0.f, er_d = 0.f;   // row r0+8
        #pragma unroll
        for (int j = 0; j < 8; j++) {
            int cn = wn + j * 8 + 2 * (lane & 3);
            float a0 = __ldg(&atl[cn]),     a1 = __ldg(&atl[cn + 1]);
            float b0 = __ldg(&atr[cn]),     b1 = __ldg(&atr[cn + 1]);
            float c0 = c_[i][j][0], c1 = c_[i][j][1];
            float c2 = c_[i][j][2], c3 = c_[i][j][3];
            if (j < 4) {
                el_a += c0 * a0 + c1 * a1;  er_a += c0 * b0 + c1 * b1;
                el_c += c2 * a0 + c3 * a1;  er_c += c2 * b0 + c3 * b1;
            } else {
                el_b += c0 * a0 + c1 * a1;  er_b += c0 * b0 + c1 * b1;
                el_d += c2 * a0 + c3 * a1;  er_d += c2 * b0 + c3 * b1;
            }
            if (r0 < N_)
                *(__half2*)&g_fth[(size_t)r0 * HD + cn] = __floats2half2_rn(c0, c1);
            if (r0 + 8 < N_)
                *(__half2*)&g_fth[(size_t)(r0 + 8) * HD + cn] = __floats2half2_rn(c2, c3);
        }
        atomicAdd(&sel[rloc0][h0w], el_a);     atomicAdd(&ser[rloc0][h0w], er_a);
        atomicAdd(&sel[rloc0][h0w + 1], el_b); atomicAdd(&ser[rloc0][h0w + 1], er_b);
        atomicAdd(&sel[rloc0 + 8][h0w], el_c);     atomicAdd(&ser[rloc0 + 8][h0w], er_c);
        atomicAdd(&sel[rloc0 + 8][h0w + 1], el_d); atomicAdd(&ser[rloc0 + 8][h0w + 1], er_d);
    }
    __syncthreads();
    #pragma unroll
    for (int idx = tid; idx < 512; idx += 256) {
        int r = idx >> 2, h = idx & 3;
        int gm = m0b + r;
        if (gm < N_) {
            g_el[gm * HH + h] = sel[r][h];
            g_er[gm * HH + h] = ser[r][h];
        }
    }
}

// ---------------- fused softmax + aggregation (measured 68-69us) ------------
// 16 lanes per dst node (2 nodes per warp), 8 channels per lane (uint4 = 16B
// gather). MLP=2 edges in flight; issue-thinned (kernel is issue-bound).
// rst = (sum_i ex_i * ft16[src_i]) / sum_i ex_i + bias  (max-free softmax)
__global__ void k_agg(const float* __restrict__ bias, float* __restrict__ out) {
    int node = (blockIdx.x * blockDim.x + threadIdx.x) >> 4;
    if (node >= N_) return;
    int sub = threadIdx.x & 15;      // lane within node group
    int h = sub >> 2;                // head (4 lanes per head, 8 ch each)
    // loop-independent loads issued up front
    float erh = __ldg(&g_er[node * HH + h]);
    float4 b0v = __ldg(&((const float4*)bias)[sub * 2]);
    float4 b1v = __ldg(&((const float4*)bias)[sub * 2 + 1]);
    int deg = g_cnt[node];
    deg = (deg < CAP) ? deg : CAP;
    const int* sl = g_srcs + (size_t)node * CAP;
    const uint4* fth = (const uint4*)g_fth;   // 16B = 8 half channels per lane
    float accA[8] = {0.f, 0.f, 0.f, 0.f, 0.f, 0.f, 0.f, 0.f};
    float accB[8] = {0.f, 0.f, 0.f, 0.f, 0.f, 0.f, 0.f, 0.f};
    float s0 = 0.f, s1 = 0.f;
    int p = 0;
    for (; p + 2 <= deg; p += 2) {
        int2 ii = __ldg((const int2*)(sl + p));   // group-uniform 8B broadcast
        float e0 = __ldg(&g_el[ii.x * HH + h]) + erh;
        float e1 = __ldg(&g_el[ii.y * HH + h]) + erh;
        uint4 u0 = __ldg(&fth[(size_t)ii.x * 16 + sub]);
        uint4 u1 = __ldg(&fth[(size_t)ii.y * 16 + sub]);
        e0 = (e0 > 0.f) ? e0 : NEG * e0;
        e1 = (e1 > 0.f) ? e1 : NEG * e1;
        float x0 = __expf(e0), x1 = __expf(e1);
        float2 a0 = __half22float2(*(__half2*)&u0.x), a1 = __half22float2(*(__half2*)&u0.y);
        float2 a2 = __half22float2(*(__half2*)&u0.z), a3 = __half22float2(*(__half2*)&u0.w);
        float2 b0 = __half22float2(*(__half2*)&u1.x), b1 = __half22float2(*(__half2*)&u1.y);
        float2 b2 = __half22float2(*(__half2*)&u1.z), b3 = __half22float2(*(__half2*)&u1.w);
        accA[0] = fmaf(x0, a0.x, accA[0]); accA[1] = fmaf(x0, a0.y, accA[1]);
        accA[2] = fmaf(x0, a1.x, accA[2]); accA[3] = fmaf(x0, a1.y, accA[3]);
        accA[4] = fmaf(x0, a2.x, accA[4]); accA[5] = fmaf(x0, a2.y, accA[5]);
        accA[6] = fmaf(x0, a3.x, accA[6]); accA[7] = fmaf(x0, a3.y, accA[7]);
        accB[0] = fmaf(x1, b0.x, accB[0]); accB[1] = fmaf(x1, b0.y, accB[1]);
        accB[2] = fmaf(x1, b1.x, accB[2]); accB[3] = fmaf(x1, b1.y, accB[3]);
        accB[4] = fmaf(x1, b2.x, accB[4]); accB[5] = fmaf(x1, b2.y, accB[5]);
        accB[6] = fmaf(x1, b3.x, accB[6]); accB[7] = fmaf(x1, b3.y, accB[7]);
        s0 += x0; s1 += x1;
    }
    if (p < deg) {
        int i0 = __ldg(&sl[p]);
        float e0 = __ldg(&g_el[i0 * HH + h]) + erh;
        uint4 u0 = __ldg(&fth[(size_t)i0 * 16 + sub]);
        e0 = (e0 > 0.f) ? e0 : NEG * e0;
        float x0 = __expf(e0);
        float2 a0 = __half22float2(*(__half2*)&u0.x), a1 = __half22float2(*(__half2*)&u0.y);
        float2 a2 = __half22float2(*(__half2*)&u0.z), a3 = __half22float2(*(__half2*)&u0.w);
        accA[0] = fmaf(x0, a0.x, accA[0]); accA[1] = fmaf(x0, a0.y, accA[1]);
        accA[2] = fmaf(x0, a1.x, accA[2]); accA[3] = fmaf(x0, a1.y, accA[3]);
        accA[4] = fmaf(x0, a2.x, accA[4]); accA[5] = fmaf(x0, a2.y, accA[5]);
        accA[6] = fmaf(x0, a3.x, accA[6]); accA[7] = fmaf(x0, a3.y, accA[7]);
        s0 += x0;
    }
    float s = s0 + s1;
    float inv = 1.f / fmaxf(s, 1e-38f);
    float4 o0, o1;
    o0.x = fmaf(accA[0] + accB[0], inv, b0v.x);
    o0.y = fmaf(accA[1] + accB[1], inv, b0v.y);
    o0.z = fmaf(accA[2] + accB[2], inv, b0v.z);
    o0.w = fmaf(accA[3] + accB[3], inv, b0v.w);
    o1.x = fmaf(accA[4] + accB[4], inv, b1v.x);
    o1.y = fmaf(accA[5] + accB[5], inv, b1v.y);
    o1.z = fmaf(accA[6] + accB[6], inv, b1v.z);
    o1.w = fmaf(accA[7] + accB[7], inv, b1v.w);
    float4* out4 = (float4*)out;
    out4[(size_t)node * 32 + sub * 2] = o0;
    out4[(size_t)node * 32 + sub * 2 + 1] = o1;
}

// ---------------- launch ----------------
extern "C" void kernel_launch(void* const* d_in, const int* in_sizes, int n_in,
                              void* d_out, int out_size) {
    const float* feat   = (const float*)d_in[0];
    const void*  src    = d_in[1];
    const void*  dst    = d_in[2];
    const float* W      = (const float*)d_in[3];
    const float* attn_l = (const float*)d_in[4];
    const float* attn_r = (const float*)d_in[5];
    const float* bias   = (const float*)d_in[6];
    float* out = (float*)d_out;

    k_init<<<(N_ + 255) / 256, 256>>>(dst);
    k_scatter<<<(E_ / 2 + 255) / 256, 256>>>(src, dst);
    k_gemm_tc<<<(N_ + 127) / 128, 256>>>(feat, W, attn_l, attn_r);
    k_agg<<<(N_ * 16 + 255) / 256, 256>>>(bias, out);
}

// round 16
// speedup vs baseline: 1.5429x; 1.0152x over previous
#include <cuda_runtime.h>
#include <cuda_fp16.h>

// Problem constants
#define N_  100000
#define E_  1600000
#define DIN 128
#define HH  4
#define DD  32
#define HD  128        // HH*DD
#define NEG 0.2f
#define CAP 96         // per-node bucket capacity (Poisson(16) tail @96 ~ 1e-50)

#define GEMM_BLOCKS ((N_ + 127) / 128)          // 782
#define SCAT_BLOCKS ((E_ / 2 + 255) / 256)      // 3125

// ---------------- device scratch (no allocations allowed) ----------------
__device__ __half g_fth[(size_t)N_ * HD];   // projected features fp16 (agg gather table)
__device__ float  g_el[N_ * HH];
__device__ float  g_er[N_ * HH];
__device__ int    g_cnt[N_];
__device__ int    g_srcs[(size_t)N_ * CAP]; // src ids bucketed by dst
__device__ int    g_is64;

// ---------------- dtype detect (int32 vs int64) + zero counters ----------
__global__ void k_init(const void* dst) {
    int i = blockIdx.x * blockDim.x + threadIdx.x;
    if (i < N_) g_cnt[i] = 0;
    if (i == 0) {
        const int* p = (const int*)dst;
        int odd_or = 0;
        // If data is int64 (values < 2^31), every odd 32-bit word is 0.
        #pragma unroll 1
        for (int j = 1; j < 64; j += 2) odd_or |= p[j];
        g_is64 = (odd_or == 0) ? 1 : 0;
    }
}

__device__ __forceinline__ int ld_idx(const void* p, int i, int is64) {
    return is64 ? (int)((const long long*)p)[i] : ((const int*)p)[i];
}

// ---------------- helpers for tf32 path ----------------
__device__ __forceinline__ float tf32r(float x) {
    unsigned r;
    asm("cvt.rna.tf32.f32 %0, %1;" : "=r"(r) : "f"(x));
    return __uint_as_float(r);
}

__device__ __forceinline__ void mma_tf32(float* c,
                                         unsigned a0, unsigned a1, unsigned a2, unsigned a3,
                                         unsigned b0, unsigned b1) {
    asm volatile("mma.sync.aligned.m16n8k8.row.col.f32.tf32.tf32.f32 "
        "{%0,%1,%2,%3}, {%4,%5,%6,%7}, {%8,%9}, {%0,%1,%2,%3};"
        : "+f"(c[0]), "+f"(c[1]), "+f"(c[2]), "+f"(c[3])
        : "r"(a0), "r"(a1), "r"(a2), "r"(a3), "r"(b0), "r"(b1));
}

// ---------------- FUSED kernel: GEMM+attn epilogue  ||  bucket scatter ------
// Blocks [0, GEMM_BLOCKS): tensor-core GEMM (tensor/LDS-bound).
// Blocks [GEMM_BLOCKS, +SCAT_BLOCKS): edge scatter (L2/atomic-bound).
// The two halves touch disjoint data and pipes; co-residency hides the
// scatter's ~25us entirely under the GEMM (they were serialized before).
__global__ void __launch_bounds__(256) k_fused(const float* __restrict__ A,
                                               const float* __restrict__ B,
                                               const float* __restrict__ atl,
                                               const float* __restrict__ atr,
                                               const void* __restrict__ src,
                                               const void* __restrict__ dst) {
    // ---------------- scatter branch ----------------
    if (blockIdx.x >= GEMM_BLOCKS) {
        int bid = blockIdx.x - GEMM_BLOCKS;
        int base = (bid * 256 + threadIdx.x) * 2;
        int is64 = g_is64;
        #pragma unroll
        for (int q = 0; q < 2; q++) {
            int i = base + q;
            if (i >= E_) return;
            int s = ld_idx(src, i, is64);
            int d = ld_idx(dst, i, is64);
            int p = atomicAdd(&g_cnt[d], 1);
            if (p < CAP) g_srcs[(size_t)d * CAP + p] = s;
        }
        return;
    }

    // ---------------- GEMM branch (identical to R15 passing version) -------
    // ft[m][n] = sum_k feat[m][k] * W[n][k]; emits fp16 table + el/er.
    // Pure 1xTF32, inputs pre-rounded at smem-store time.
    __shared__ float As[32][132];   // As[k][m], values pre-rounded to tf32
    __shared__ float Bs[32][132];   // Bs[k][n]  (= W[n][k]), pre-rounded
    __shared__ float sel[128][4];
    __shared__ float ser[128][4];
    int tid = threadIdx.x;
    int lane = tid & 31;
    int warp = tid >> 5;
    int m0b = blockIdx.x * 128;
    int wm = (warp >> 1) * 32;      // warp M offset in block
    int wn = (warp & 1) * 64;       // warp N offset in block

    // zero el/er accumulators
    #pragma unroll
    for (int idx = tid; idx < 512; idx += 256) {
        sel[idx >> 2][idx & 3] = 0.f;
        ser[idx >> 2][idx & 3] = 0.f;
    }

    float c_[2][8][4];
    #pragma unroll
    for (int i = 0; i < 2; i++)
        #pragma unroll
        for (int j = 0; j < 8; j++)
            #pragma unroll
            for (int q = 0; q < 4; q++) c_[i][j][q] = 0.f;

    for (int kt = 0; kt < DIN; kt += 32) {
        #pragma unroll
        for (int l = 0; l < 4; l++) {
            int idx = tid + l * 256;       // 0..1023
            int r = idx >> 3, c4 = idx & 7;
            int gm = m0b + r;
            float4 va = make_float4(0.f, 0.f, 0.f, 0.f);
            if (gm < N_) va = *(const float4*)(A + (size_t)gm * DIN + kt + c4 * 4);
            As[c4 * 4 + 0][r] = tf32r(va.x); As[c4 * 4 + 1][r] = tf32r(va.y);
            As[c4 * 4 + 2][r] = tf32r(va.z); As[c4 * 4 + 3][r] = tf32r(va.w);
            float4 vb = *(const float4*)(B + (size_t)r * DIN + kt + c4 * 4);
            Bs[c4 * 4 + 0][r] = tf32r(vb.x); Bs[c4 * 4 + 1][r] = tf32r(vb.y);
            Bs[c4 * 4 + 2][r] = tf32r(vb.z); Bs[c4 * 4 + 3][r] = tf32r(vb.w);
        }
        __syncthreads();
        #pragma unroll
        for (int ks = 0; ks < 32; ks += 8) {
            unsigned ah[2][4];
            #pragma unroll
            for (int i = 0; i < 2; i++) {
                int r = wm + i * 16 + (lane >> 2);
                int kk = ks + (lane & 3);
                ah[i][0] = __float_as_uint(As[kk][r]);
                ah[i][1] = __float_as_uint(As[kk][r + 8]);
                ah[i][2] = __float_as_uint(As[kk + 4][r]);
                ah[i][3] = __float_as_uint(As[kk + 4][r + 8]);
            }
            #pragma unroll
            for (int j = 0; j < 8; j++) {
                int cn = wn + j * 8 + (lane >> 2);
                int kk = ks + (lane & 3);
                unsigned bh0 = __float_as_uint(Bs[kk][cn]);
                unsigned bh1 = __float_as_uint(Bs[kk + 4][cn]);
                #pragma unroll
                for (int i = 0; i < 2; i++)
                    mma_tf32(c_[i][j], ah[i][0], ah[i][1], ah[i][2], ah[i][3], bh0, bh1);
            }
        }
        __syncthreads();
    }

    // ---- epilogue: store fp16 ft, accumulate el/er into smem ----
    int h0w = wn >> 5;                // first head covered by this warp (j=0..3)
    #pragma unroll
    for (int i = 0; i < 2; i++) {
        int rloc0 = wm + i * 16 + (lane >> 2);  // local row (0..127)
        int r0 = m0b + rloc0;
        float el_a = 0.f, er_a = 0.f, el_b = 0.f, er_b = 0.f;   // row r0: head h0w, h0w+1
        float el_c = 0.f, er_c = 0.f, el_d = 0.f, er_d = 0.f;   // row r0+8
        #pragma unroll
        for (int j = 0; j < 8; j++) {
            int cn = wn + j * 8 + 2 * (lane & 3);
            float a0 = __ldg(&atl[cn]),     a1 = __ldg(&atl[cn + 1]);
            float b0 = __ldg(&atr[cn]),     b1 = __ldg(&atr[cn + 1]);
            float c0 = c_[i][j][0], c1 = c_[i][j][1];
            float c2 = c_[i][j][2], c3 = c_[i][j][3];
            if (j < 4) {
                el_a += c0 * a0 + c1 * a1;  er_a += c0 * b0 + c1 * b1;
                el_c += c2 * a0 + c3 * a1;  er_c += c2 * b0 + c3 * b1;
            } else {
                el_b += c0 * a0 + c1 * a1;  er_b += c0 * b0 + c1 * b1;
                el_d += c2 * a0 + c3 * a1;  er_d += c2 * b0 + c3 * b1;
            }
            if (r0 < N_)
                *(__half2*)&g_fth[(size_t)r0 * HD + cn] = __floats2half2_rn(c0, c1);
            if (r0 + 8 < N_)
                *(__half2*)&g_fth[(size_t)(r0 + 8) * HD + cn] = __floats2half2_rn(c2, c3);
        }
        atomicAdd(&sel[rloc0][h0w], el_a);     atomicAdd(&ser[rloc0][h0w], er_a);
        atomicAdd(&sel[rloc0][h0w + 1], el_b); atomicAdd(&ser[rloc0][h0w + 1], er_b);
        atomicAdd(&sel[rloc0 + 8][h0w], el_c);     atomicAdd(&ser[rloc0 + 8][h0w], er_c);
        atomicAdd(&sel[rloc0 + 8][h0w + 1], el_d); atomicAdd(&ser[rloc0 + 8][h0w + 1], er_d);
    }
    __syncthreads();
    #pragma unroll
    for (int idx = tid; idx < 512; idx += 256) {
        int r = idx >> 2, h = idx & 3;
        int gm = m0b + r;
        if (gm < N_) {
            g_el[gm * HH + h] = sel[r][h];
            g_er[gm * HH + h] = ser[r][h];
        }
    }
}

// ---------------- fused softmax + aggregation (measured 68-69us) ------------
// 16 lanes per dst node (2 nodes per warp), 8 channels per lane (uint4 = 16B
// gather). MLP=2 edges in flight; issue-thinned (kernel is issue-bound).
// rst = (sum_i ex_i * ft16[src_i]) / sum_i ex_i + bias  (max-free softmax)
__global__ void k_agg(const float* __restrict__ bias, float* __restrict__ out) {
    int node = (blockIdx.x * blockDim.x + threadIdx.x) >> 4;
    if (node >= N_) return;
    int sub = threadIdx.x & 15;      // lane within node group
    int h = sub >> 2;                // head (4 lanes per head, 8 ch each)
    // loop-independent loads issued up front
    float erh = __ldg(&g_er[node * HH + h]);
    float4 b0v = __ldg(&((const float4*)bias)[sub * 2]);
    float4 b1v = __ldg(&((const float4*)bias)[sub * 2 + 1]);
    int deg = g_cnt[node];
    deg = (deg < CAP) ? deg : CAP;
    const int* sl = g_srcs + (size_t)node * CAP;
    const uint4* fth = (const uint4*)g_fth;   // 16B = 8 half channels per lane
    float accA[8] = {0.f, 0.f, 0.f, 0.f, 0.f, 0.f, 0.f, 0.f};
    float accB[8] = {0.f, 0.f, 0.f, 0.f, 0.f, 0.f, 0.f, 0.f};
    float s0 = 0.f, s1 = 0.f;
    int p = 0;
    for (; p + 2 <= deg; p += 2) {
        int2 ii = __ldg((const int2*)(sl + p));   // group-uniform 8B broadcast
        float e0 = __ldg(&g_el[ii.x * HH + h]) + erh;
        float e1 = __ldg(&g_el[ii.y * HH + h]) + erh;
        uint4 u0 = __ldg(&fth[(size_t)ii.x * 16 + sub]);
        uint4 u1 = __ldg(&fth[(size_t)ii.y * 16 + sub]);
        e0 = (e0 > 0.f) ? e0 : NEG * e0;
        e1 = (e1 > 0.f) ? e1 : NEG * e1;
        float x0 = __expf(e0), x1 = __expf(e1);
        float2 a0 = __half22float2(*(__half2*)&u0.x), a1 = __half22float2(*(__half2*)&u0.y);
        float2 a2 = __half22float2(*(__half2*)&u0.z), a3 = __half22float2(*(__half2*)&u0.w);
        float2 b0 = __half22float2(*(__half2*)&u1.x), b1 = __half22float2(*(__half2*)&u1.y);
        float2 b2 = __half22float2(*(__half2*)&u1.z), b3 = __half22float2(*(__half2*)&u1.w);
        accA[0] = fmaf(x0, a0.x, accA[0]); accA[1] = fmaf(x0, a0.y, accA[1]);
        accA[2] = fmaf(x0, a1.x, accA[2]); accA[3] = fmaf(x0, a1.y, accA[3]);
        accA[4] = fmaf(x0, a2.x, accA[4]); accA[5] = fmaf(x0, a2.y, accA[5]);
        accA[6] = fmaf(x0, a3.x, accA[6]); accA[7] = fmaf(x0, a3.y, accA[7]);
        accB[0] = fmaf(x1, b0.x, accB[0]); accB[1] = fmaf(x1, b0.y, accB[1]);
        accB[2] = fmaf(x1, b1.x, accB[2]); accB[3] = fmaf(x1, b1.y, accB[3]);
        accB[4] = fmaf(x1, b2.x, accB[4]); accB[5] = fmaf(x1, b2.y, accB[5]);
        accB[6] = fmaf(x1, b3.x, accB[6]); accB[7] = fmaf(x1, b3.y, accB[7]);
        s0 += x0; s1 += x1;
    }
    if (p < deg) {
        int i0 = __ldg(&sl[p]);
        float e0 = __ldg(&g_el[i0 * HH + h]) + erh;
        uint4 u0 = __ldg(&fth[(size_t)i0 * 16 + sub]);
        e0 = (e0 > 0.f) ? e0 : NEG * e0;
        float x0 = __expf(e0);
        float2 a0 = __half22float2(*(__half2*)&u0.x), a1 = __half22float2(*(__half2*)&u0.y);
        float2 a2 = __half22float2(*(__half2*)&u0.z), a3 = __half22float2(*(__half2*)&u0.w);
        accA[0] = fmaf(x0, a0.x, accA[0]); accA[1] = fmaf(x0, a0.y, accA[1]);
        accA[2] = fmaf(x0, a1.x, accA[2]); accA[3] = fmaf(x0, a1.y, accA[3]);
        accA[4] = fmaf(x0, a2.x, accA[4]); accA[5] = fmaf(x0, a2.y, accA[5]);
        accA[6] = fmaf(x0, a3.x, accA[6]); accA[7] = fmaf(x0, a3.y, accA[7]);
        s0 += x0;
    }
    float s = s0 + s1;
    float inv = 1.f / fmaxf(s, 1e-38f);
    float4 o0, o1;
    o0.x = fmaf(accA[0] + accB[0], inv, b0v.x);
    o0.y = fmaf(accA[1] + accB[1], inv, b0v.y);
    o0.z = fmaf(accA[2] + accB[2], inv, b0v.z);
    o0.w = fmaf(accA[3] + accB[3], inv, b0v.w);
    o1.x = fmaf(accA[4] + accB[4], inv, b1v.x);
    o1.y = fmaf(accA[5] + accB[5], inv, b1v.y);
    o1.z = fmaf(accA[6] + accB[6], inv, b1v.z);
    o1.w = fmaf(accA[7] + accB[7], inv, b1v.w);
    float4* out4 = (float4*)out;
    out4[(size_t)node * 32 + sub * 2] = o0;
    out4[(size_t)node * 32 + sub * 2 + 1] = o1;
}

// ---------------- launch ----------------
extern "C" void kernel_launch(void* const* d_in, const int* in_sizes, int n_in,
                              void* d_out, int out_size) {
    const float* feat   = (const float*)d_in[0];
    const void*  src    = d_in[1];
    const void*  dst    = d_in[2];
    const float* W      = (const float*)d_in[3];
    const float* attn_l = (const float*)d_in[4];
    const float* attn_r = (const float*)d_in[5];
    const float* bias   = (const float*)d_in[6];
    float* out = (float*)d_out;

    k_init<<<(N_ + 255) / 256, 256>>>(dst);
    k_fused<<<GEMM_BLOCKS + SCAT_BLOCKS, 256>>>(feat, W, attn_l, attn_r, src, dst);
    k_agg<<<(N_ * 16 + 255) / 256, 256>>>(bias, out);
}